// round 8
// baseline (speedup 1.0000x reference)
#include <cuda_runtime.h>
#include <cuda_bf16.h>
#include <math.h>

// ---------------------------------------------------------------------------
// Problem constants
// ---------------------------------------------------------------------------
#define B_     8
#define N_     8192
#define S_     2048      // NPOINT
#define K_     32        // NSAMPLE
#define C_     64        // feature channels
#define D0     67        // 3 + 64
#define D1     64
#define D2     64
#define D3     128
#define R2     0.04f
#define EPSV   1e-5f

typedef unsigned long long ull;
typedef unsigned int uint;

// ---------------------------------------------------------------------------
// f32x2 packed helpers (sm_100+): two independent RN fp32 lanes per op.
// ---------------------------------------------------------------------------
__device__ __forceinline__ ull pack2(float lo, float hi) {
    ull r; asm("mov.b64 %0, {%1, %2};" : "=l"(r) : "f"(lo), "f"(hi)); return r;
}
__device__ __forceinline__ void unpack2(ull v, float& lo, float& hi) {
    asm("mov.b64 {%0, %1}, %2;" : "=f"(lo), "=f"(hi) : "l"(v));
}
__device__ __forceinline__ ull add2_(ull a, ull b) {
    ull r; asm("add.rn.f32x2 %0, %1, %2;" : "=l"(r) : "l"(a), "l"(b)); return r;
}
__device__ __forceinline__ ull mul2_(ull a, ull b) {
    ull r; asm("mul.rn.f32x2 %0, %1, %2;" : "=l"(r) : "l"(a), "l"(b)); return r;
}
__device__ __forceinline__ ull fma2_(ull a, ull b, ull c) {
    ull r; asm("fma.rn.f32x2 %0, %1, %2, %3;" : "=l"(r) : "l"(a), "l"(b), "l"(c)); return r;
}

// ---------------------------------------------------------------------------
// release/acquire progress primitives (gpu scope)
// ---------------------------------------------------------------------------
__device__ __forceinline__ void st_release(int* p, int v) {
    asm volatile("st.release.gpu.s32 [%0], %1;" :: "l"(p), "r"(v) : "memory");
}
__device__ __forceinline__ int ld_acquire(const int* p) {
    int v; asm volatile("ld.acquire.gpu.s32 %0, [%1];" : "=r"(v) : "l"(p) : "memory");
    return v;
}

// ---------------------------------------------------------------------------
// Scratch (device globals)
// ---------------------------------------------------------------------------
__device__ __align__(16) float g_featT[B_ * N_ * C_];   // (B, N, C), 16 MB
__device__ __align__(16) float g_wT0[D0 * D1];          // [c][o], scale-folded
__device__ __align__(16) float g_wT1[D1 * D2];
__device__ __align__(16) float g_wT2[D2 * D3];
__device__ __align__(16) float g_off0[D1];
__device__ __align__(16) float g_off1[D2];
__device__ __align__(16) float g_off2[D3];
__device__ int g_progress[B_];                          // centers visible per batch

// ---------------------------------------------------------------------------
// Kernel 1: transpose features (B, C, N) -> (B, N, C).
// Block (0,0,0) additionally folds BN into weights and resets progress.
// ---------------------------------------------------------------------------
__global__ void transpose_prep_kernel(const float* __restrict__ f,
    const float* __restrict__ w0, const float* __restrict__ b0,
    const float* __restrict__ g0, const float* __restrict__ be0,
    const float* __restrict__ m0, const float* __restrict__ v0,
    const float* __restrict__ w1, const float* __restrict__ b1,
    const float* __restrict__ g1, const float* __restrict__ be1,
    const float* __restrict__ m1, const float* __restrict__ v1,
    const float* __restrict__ w2, const float* __restrict__ b2,
    const float* __restrict__ g2, const float* __restrict__ be2,
    const float* __restrict__ m2, const float* __restrict__ v2)
{
    __shared__ float tile[32][33];
    int b  = blockIdx.z;
    int c0 = blockIdx.y * 32;
    int n0 = blockIdx.x * 32;
    int tx = threadIdx.x, ty = threadIdx.y;

    if (blockIdx.x == 0 && blockIdx.y == 0 && blockIdx.z == 0) {
        int t = ty * 32 + tx;                  // 0..255
        if (t < B_) g_progress[t] = 0;
        for (int o = t; o < D1; o += 256) {
            float sc = g0[o] * rsqrtf(v0[o] + EPSV);
            g_off0[o] = (b0[o] - m0[o]) * sc + be0[o];
            for (int c = 0; c < D0; c++) g_wT0[c * D1 + o] = w0[o * D0 + c] * sc;
        }
        for (int o = t; o < D2; o += 256) {
            float sc = g1[o] * rsqrtf(v1[o] + EPSV);
            g_off1[o] = (b1[o] - m1[o]) * sc + be1[o];
            for (int c = 0; c < D1; c++) g_wT1[c * D2 + o] = w1[o * D1 + c] * sc;
        }
        for (int o = t; o < D3; o += 256) {
            float sc = g2[o] * rsqrtf(v2[o] + EPSV);
            g_off2[o] = (b2[o] - m2[o]) * sc + be2[o];
            for (int c = 0; c < D2; c++) g_wT2[c * D3 + o] = w2[o * D2 + c] * sc;
        }
    }

    #pragma unroll
    for (int i = ty; i < 32; i += 8)
        tile[i][tx] = f[((size_t)b * C_ + (c0 + i)) * N_ + n0 + tx];
    __syncthreads();
    #pragma unroll
    for (int i = ty; i < 32; i += 8)
        g_featT[((size_t)b * N_ + (n0 + i)) * C_ + c0 + tx] = tile[tx][i];
}

// ---------------------------------------------------------------------------
// Merged kernel: blocks 0..7 = FPS producers; blocks 8.. = ball+MLP consumers.
// ---------------------------------------------------------------------------
#define FPS_T 512
#define FPS_J 16
#define FPS_Q 8
#define FPS_W (FPS_T / 32)

#define SK 36
#define A_ELEMS   (68 * SK)
#define BB_ELEMS  (64 * SK)
#define GSTRIDE   (A_ELEMS + BB_ELEMS)
#define W_ELEMS   (D2 * D3)
#define GRP_BASE  W_ELEMS
#define INT_BASE  (W_ELEMS + 4 * GSTRIDE)
#define MERGED_SMEM (115 * 1024)         // force 1 block/SM

#define NCONS_BLK 4096                   // consumer blocks (4 centers each)

__global__ void __launch_bounds__(FPS_T, 1)
merged_kernel(const float* __restrict__ xyz,
              float* __restrict__ newxyz,
              float* __restrict__ outp)
{
    extern __shared__ float dyn[];
    const int t = threadIdx.x;
    const unsigned FULL = 0xffffffffu;

    if (blockIdx.x < B_) {
        // =================== FPS producer (one barrier per iteration) =========
        float* sxn = dyn;                  // NEGATED coords mirrors
        float* syn = dyn + N_;
        float* szn = dyn + 2 * N_;
        ull*   sKey = (ull*)(dyn + 3 * N_); // [2] (maxbits<<32)|(8191-idx)

        const int b    = blockIdx.x;
        const int lane = t & 31;
        const float* X = xyz + (size_t)b * N_ * 3;

        ull pX[FPS_Q], pY[FPS_Q], pZ[FPS_Q];
        uint ddu[FPS_J];
        const uint INF_BITS = __float_as_uint(1e10f);
        #pragma unroll
        for (int q = 0; q < FPS_Q; q++) {
            int p0 = t + (2 * q) * FPS_T;
            int p1 = t + (2 * q + 1) * FPS_T;
            float x0 = X[p0 * 3 + 0], y0 = X[p0 * 3 + 1], z0 = X[p0 * 3 + 2];
            float x1 = X[p1 * 3 + 0], y1 = X[p1 * 3 + 1], z1 = X[p1 * 3 + 2];
            pX[q] = pack2(x0, x1); pY[q] = pack2(y0, y1); pZ[q] = pack2(z0, z1);
            sxn[p0] = -x0; syn[p0] = -y0; szn[p0] = -z0;
            sxn[p1] = -x1; syn[p1] = -y1; szn[p1] = -z1;
            ddu[2 * q] = INF_BITS; ddu[2 * q + 1] = INF_BITS;
        }
        if (t == 0) { sKey[0] = 0ULL; sKey[1] = 0ULL; }
        __syncthreads();

        int cidx = 0;
        if (t == 0) {
            float* o = newxyz + (size_t)b * S_ * 3;
            o[0] = -sxn[0]; o[1] = -syn[0]; o[2] = -szn[0];
        }

        for (int i = 0; i < S_; i++) {
            const int buf = i & 1;
            const float nx = sxn[cidx], ny = syn[cidx], nz = szn[cidx]; // -c
            const ull ncx = pack2(nx, nx);
            const ull ncy = pack2(ny, ny);
            const ull ncz = pack2(nz, nz);

            #pragma unroll
            for (int q = 0; q < FPS_Q; q++) {
                ull dX = add2_(pX[q], ncx);
                ull dY = add2_(pY[q], ncy);
                ull dZ = add2_(pZ[q], ncz);
                ull d2 = add2_(add2_(mul2_(dX, dX), mul2_(dY, dY)), mul2_(dZ, dZ));
                float dlo, dhi; unpack2(d2, dlo, dhi);
                ddu[2 * q]     = min(ddu[2 * q],     __float_as_uint(dlo));
                ddu[2 * q + 1] = min(ddu[2 * q + 1], __float_as_uint(dhi));
            }
            // per-thread max tree (ALU pipe)
            uint m0 = max(max(ddu[0], ddu[1]),   max(ddu[2], ddu[3]));
            uint m1 = max(max(ddu[4], ddu[5]),   max(ddu[6], ddu[7]));
            uint m2 = max(max(ddu[8], ddu[9]),   max(ddu[10], ddu[11]));
            uint m3 = max(max(ddu[12], ddu[13]), max(ddu[14], ddu[15]));
            uint bvu = max(max(m0, m1), max(m2, m3));

            // per-thread min-j matching own max (descending sel chain)
            int myj = 15;
            #pragma unroll
            for (int j = 14; j >= 0; j--) myj = (ddu[j] == bvu) ? j : myj;

            // warp: max value, then min index among holders
            uint wmax = __reduce_max_sync(FULL, bvu);
            uint cand = (bvu == wmax) ? (uint)(t + myj * FPS_T) : 0xffffffffu;
            uint widx = __reduce_min_sync(FULL, cand);

            // one 64-bit key atomic per warp; max key == (max val, min idx)
            if (lane == 0)
                atomicMax(&sKey[buf], ((ull)wmax << 32) | (ull)(8191u - widx));
            __syncthreads();                      // single barrier (drains atomics)

            // t0 resets the other-parity slot; next writers are a full dist
            // loop (>=400 cyc) away, t0 issues within ~RR latency -> safe.
            if (t == 0) sKey[buf ^ 1] = 0ULL;

            ull key = sKey[buf];
            cidx = 8191 - (int)((uint)key & 0x1FFFu);

            if (t == 0) {
                if (i < S_ - 1) {
                    float* o = newxyz + ((size_t)b * S_ + i + 1) * 3;
                    o[0] = -sxn[cidx]; o[1] = -syn[cidx]; o[2] = -szn[cidx];
                }
                if ((i & 7) == 7) {
                    int vis = (i < S_ - 1) ? (i + 2) : S_;
                    st_release(&g_progress[b], vis);
                }
            }
        }
        return;
    }

    // =================== consumer: ball query + MLP for 4 centers ===================
    const int cb = blockIdx.x - B_;           // 0..4095
    const int b  = cb & 7;                    // batch (interleaved)
    const int s0 = (cb >> 3) * 4;             // first center of this block

    float* W  = dyn;                          // [8192]
    const int gg  = t >> 7;                   // group 0..3
    const int gt  = t & 127;                  // thread within group
    const int gw  = gt >> 5;                  // warp within group
    const int lane = t & 31;

    float* A  = dyn + GRP_BASE + gg * GSTRIDE;
    float* Bb = A + A_ELEMS;
    int* iBase = (int*)(dyn + INT_BASE);
    int* sBall = iBase + gg * 128;
    int* sCnt  = iBase + 512 + gg * 4;
    int* sIdxG = iBase + 528 + gg * K_;

    if (t == 0) {
        while (ld_acquire(&g_progress[b]) < s0 + 4) __nanosleep(64);
    }
    __syncthreads();

    const int s   = s0 + gg;
    const int cid = b * S_ + s;
    const float* cc = newxyz + (size_t)cid * 3;
    const float cx = cc[0], cy = cc[1], cz = cc[2];
    const float* X = xyz + (size_t)b * N_ * 3;

    // --- ball query: warp gw scans [gw*2048, (gw+1)*2048) ---
    {
        int myCnt = 0;
        const unsigned lt = (1u << lane) - 1u;
        const int nEnd = (gw + 1) * (N_ / 4);
        for (int n0 = gw * (N_ / 4); n0 < nEnd && myCnt < K_; n0 += 32) {
            int p = n0 + lane;
            float dx = X[p * 3 + 0] - cx;
            float dy = X[p * 3 + 1] - cy;
            float dz = X[p * 3 + 2] - cz;
            float d  = fmaf(dz, dz, fmaf(dy, dy, dx * dx));
            bool inside = (d <= R2);
            unsigned m = __ballot_sync(FULL, inside);
            if (m) {
                int pos = myCnt + __popc(m & lt);
                if (inside && pos < K_) sBall[gw * K_ + pos] = p;
                myCnt += __popc(m);
            }
        }
        if (lane == 0) sCnt[gw] = min(myCnt, K_);
    }
    __syncthreads();

    // --- merge first-32 in ascending order; pad with overall first hit ---
    if (gt < K_) {
        int c0 = sCnt[0], c1 = sCnt[1], c2 = sCnt[2], c3 = sCnt[3];
        int o1 = c0, o2 = c0 + c1, o3 = o2 + c2, tot = o3 + c3;
        int k = gt, idx;
        if (k < tot) {
            if (k < o1)      idx = sBall[k];
            else if (k < o2) idx = sBall[32 + (k - o1)];
            else if (k < o3) idx = sBall[64 + (k - o2)];
            else             idx = sBall[96 + (k - o3)];
        } else {
            int fw = c0 ? 0 : (c1 ? 1 : (c2 ? 2 : 3));
            idx = sBall[fw * 32];
        }
        sIdxG[gt] = idx;
        const float* P = X + (size_t)idx * 3;
        A[0 * SK + gt] = P[0] - cx;
        A[1 * SK + gt] = P[1] - cy;
        A[2 * SK + gt] = P[2] - cz;
    }
    __syncthreads();

    for (int idx = gt; idx < K_ * C_; idx += 128) {
        int k = idx >> 6, c = idx & 63;
        A[(3 + c) * SK + k] = g_featT[((size_t)b * N_ + sIdxG[k]) * C_ + c];
    }
    for (int idx = t * 4; idx < D0 * D1; idx += FPS_T * 4)
        *(float4*)&W[idx] = *(const float4*)&g_wT0[idx];
    __syncthreads();

    const int kg = gt >> 4;
    const int k0 = kg * 4;
    const int og = gt & 15;

    // ================= layer 1: 67 -> 64 =================
    {
        const int o0 = og * 4;
        ull a01[4], a23[4];
        const ull z = pack2(0.0f, 0.0f);
        #pragma unroll
        for (int o = 0; o < 4; o++) { a01[o] = z; a23[o] = z; }
        #pragma unroll 4
        for (int c = 0; c < D0; c++) {
            double2 iv = *(double2*)&A[c * SK + k0];
            ull i01 = __double_as_longlong(iv.x);
            ull i23 = __double_as_longlong(iv.y);
            float4 wv = *(float4*)&W[c * D1 + o0];
            ull w2[4] = {pack2(wv.x, wv.x), pack2(wv.y, wv.y),
                         pack2(wv.z, wv.z), pack2(wv.w, wv.w)};
            #pragma unroll
            for (int o = 0; o < 4; o++) {
                a01[o] = fma2_(i01, w2[o], a01[o]);
                a23[o] = fma2_(i23, w2[o], a23[o]);
            }
        }
        float4 off = *(const float4*)&g_off0[o0];
        const float off4[4] = {off.x, off.y, off.z, off.w};
        __syncthreads();
        #pragma unroll
        for (int o = 0; o < 4; o++) {
            float4 v; float lo, hi;
            unpack2(a01[o], lo, hi);
            v.x = fmaxf(lo + off4[o], 0.0f);
            v.y = fmaxf(hi + off4[o], 0.0f);
            unpack2(a23[o], lo, hi);
            v.z = fmaxf(lo + off4[o], 0.0f);
            v.w = fmaxf(hi + off4[o], 0.0f);
            *(float4*)&Bb[(o0 + o) * SK + k0] = v;
        }
    }
    __syncthreads();
    for (int idx = t * 4; idx < D1 * D2; idx += FPS_T * 4)
        *(float4*)&W[idx] = *(const float4*)&g_wT1[idx];
    __syncthreads();

    // ================= layer 2: 64 -> 64 (Bb -> A) =================
    {
        const int o0 = og * 4;
        ull a01[4], a23[4];
        const ull z = pack2(0.0f, 0.0f);
        #pragma unroll
        for (int o = 0; o < 4; o++) { a01[o] = z; a23[o] = z; }
        #pragma unroll 4
        for (int c = 0; c < D1; c++) {
            double2 iv = *(double2*)&Bb[c * SK + k0];
            ull i01 = __double_as_longlong(iv.x);
            ull i23 = __double_as_longlong(iv.y);
            float4 wv = *(float4*)&W[c * D2 + o0];
            ull w2[4] = {pack2(wv.x, wv.x), pack2(wv.y, wv.y),
                         pack2(wv.z, wv.z), pack2(wv.w, wv.w)};
            #pragma unroll
            for (int o = 0; o < 4; o++) {
                a01[o] = fma2_(i01, w2[o], a01[o]);
                a23[o] = fma2_(i23, w2[o], a23[o]);
            }
        }
        float4 off = *(const float4*)&g_off1[o0];
        const float off4[4] = {off.x, off.y, off.z, off.w};
        __syncthreads();
        #pragma unroll
        for (int o = 0; o < 4; o++) {
            float4 v; float lo, hi;
            unpack2(a01[o], lo, hi);
            v.x = fmaxf(lo + off4[o], 0.0f);
            v.y = fmaxf(hi + off4[o], 0.0f);
            unpack2(a23[o], lo, hi);
            v.z = fmaxf(lo + off4[o], 0.0f);
            v.w = fmaxf(hi + off4[o], 0.0f);
            *(float4*)&A[(o0 + o) * SK + k0] = v;
        }
    }
    __syncthreads();
    for (int idx = t * 4; idx < D2 * D3; idx += FPS_T * 4)
        *(float4*)&W[idx] = *(const float4*)&g_wT2[idx];
    __syncthreads();

    // ================= layer 3: 64 -> 128, max over k =================
    {
        const int o0 = og * 8;
        ull a01[8], a23[8];
        const ull z = pack2(0.0f, 0.0f);
        #pragma unroll
        for (int o = 0; o < 8; o++) { a01[o] = z; a23[o] = z; }
        #pragma unroll 2
        for (int c = 0; c < D2; c++) {
            double2 iv = *(double2*)&A[c * SK + k0];
            ull i01 = __double_as_longlong(iv.x);
            ull i23 = __double_as_longlong(iv.y);
            float4 wv0 = *(float4*)&W[c * D3 + o0];
            float4 wv1 = *(float4*)&W[c * D3 + o0 + 4];
            ull w2[8] = {pack2(wv0.x, wv0.x), pack2(wv0.y, wv0.y),
                         pack2(wv0.z, wv0.z), pack2(wv0.w, wv0.w),
                         pack2(wv1.x, wv1.x), pack2(wv1.y, wv1.y),
                         pack2(wv1.z, wv1.z), pack2(wv1.w, wv1.w)};
            #pragma unroll
            for (int o = 0; o < 8; o++) {
                a01[o] = fma2_(i01, w2[o], a01[o]);
                a23[o] = fma2_(i23, w2[o], a23[o]);
            }
        }
        __syncthreads();
        #pragma unroll
        for (int o = 0; o < 8; o++) {
            float off = g_off2[o0 + o];
            float l0, h0, l1, h1;
            unpack2(a01[o], l0, h0);
            unpack2(a23[o], l1, h1);
            float m = fmaxf(fmaxf(l0, h0), fmaxf(l1, h1));
            Bb[kg * D3 + o0 + o] = fmaxf(m + off, 0.0f);
        }
    }
    __syncthreads();
    if (gt < D3) {
        float v = Bb[gt];
        #pragma unroll
        for (int g = 1; g < 8; g++) v = fmaxf(v, Bb[g * D3 + gt]);
        outp[((size_t)b * D3 + gt) * S_ + s] = v;
    }
}

// ---------------------------------------------------------------------------
// Launch
// ---------------------------------------------------------------------------
extern "C" void kernel_launch(void* const* d_in, const int* in_sizes, int n_in,
                              void* d_out, int out_size)
{
    const float* xyz  = (const float*)d_in[0];
    const float* feat = (const float*)d_in[1];

    float* out     = (float*)d_out;
    float* newxyz  = out;                       // (8, 2048, 3)
    float* mlpOut  = out + (size_t)B_ * S_ * 3; // (8, 128, 2048)

    cudaFuncSetAttribute(merged_kernel, cudaFuncAttributeMaxDynamicSharedMemorySize,
                         MERGED_SMEM);

    dim3 tg(N_ / 32, C_ / 32, B_);
    transpose_prep_kernel<<<tg, dim3(32, 8)>>>(feat,
        (const float*)d_in[2],  (const float*)d_in[3],  (const float*)d_in[4],
        (const float*)d_in[5],  (const float*)d_in[6],  (const float*)d_in[7],
        (const float*)d_in[8],  (const float*)d_in[9],  (const float*)d_in[10],
        (const float*)d_in[11], (const float*)d_in[12], (const float*)d_in[13],
        (const float*)d_in[14], (const float*)d_in[15], (const float*)d_in[16],
        (const float*)d_in[17], (const float*)d_in[18], (const float*)d_in[19]);

    merged_kernel<<<B_ + NCONS_BLK, FPS_T, MERGED_SMEM>>>(xyz, newxyz, mlpOut);
}

// round 9
// speedup vs baseline: 1.2588x; 1.2588x over previous
#include <cuda_runtime.h>
#include <cuda_bf16.h>
#include <math.h>

// ---------------------------------------------------------------------------
// Problem constants
// ---------------------------------------------------------------------------
#define B_     8
#define N_     8192
#define S_     2048      // NPOINT
#define K_     32        // NSAMPLE
#define C_     64        // feature channels
#define D0     67        // 3 + 64
#define D1     64
#define D2     64
#define D3     128
#define R2     0.04f
#define EPSV   1e-5f

typedef unsigned long long ull;
typedef unsigned int uint;

// ---------------------------------------------------------------------------
// f32x2 packed helpers (sm_100+): two independent RN fp32 lanes per op.
// ---------------------------------------------------------------------------
__device__ __forceinline__ ull pack2(float lo, float hi) {
    ull r; asm("mov.b64 %0, {%1, %2};" : "=l"(r) : "f"(lo), "f"(hi)); return r;
}
__device__ __forceinline__ void unpack2(ull v, float& lo, float& hi) {
    asm("mov.b64 {%0, %1}, %2;" : "=f"(lo), "=f"(hi) : "l"(v));
}
__device__ __forceinline__ ull add2_(ull a, ull b) {
    ull r; asm("add.rn.f32x2 %0, %1, %2;" : "=l"(r) : "l"(a), "l"(b)); return r;
}
__device__ __forceinline__ ull mul2_(ull a, ull b) {
    ull r; asm("mul.rn.f32x2 %0, %1, %2;" : "=l"(r) : "l"(a), "l"(b)); return r;
}
__device__ __forceinline__ ull fma2_(ull a, ull b, ull c) {
    ull r; asm("fma.rn.f32x2 %0, %1, %2, %3;" : "=l"(r) : "l"(a), "l"(b), "l"(c)); return r;
}

// ---------------------------------------------------------------------------
// release/acquire progress primitives (gpu scope)
// ---------------------------------------------------------------------------
__device__ __forceinline__ void st_release(int* p, int v) {
    asm volatile("st.release.gpu.s32 [%0], %1;" :: "l"(p), "r"(v) : "memory");
}
__device__ __forceinline__ int ld_acquire(const int* p) {
    int v; asm volatile("ld.acquire.gpu.s32 %0, [%1];" : "=r"(v) : "l"(p) : "memory");
    return v;
}

// ---------------------------------------------------------------------------
// Scratch (device globals)
// ---------------------------------------------------------------------------
__device__ __align__(16) float g_featT[B_ * N_ * C_];   // (B, N, C), 16 MB
__device__ __align__(16) float g_wT0[D0 * D1];          // [c][o], scale-folded
__device__ __align__(16) float g_wT1[D1 * D2];
__device__ __align__(16) float g_wT2[D2 * D3];
__device__ __align__(16) float g_off0[D1];
__device__ __align__(16) float g_off1[D2];
__device__ __align__(16) float g_off2[D3];
__device__ int g_progress[B_];                          // centers visible per batch

// ---------------------------------------------------------------------------
// Kernel 1: transpose features (B, C, N) -> (B, N, C).
// Blocks (x<3, y==0, z==0) fold BN into weight layer x (flattened, parallel).
// Block (3,0,0) resets progress counters.
// ---------------------------------------------------------------------------
__device__ __forceinline__ void fold_layer(
    const float* __restrict__ wsrc, const float* __restrict__ bsrc,
    const float* __restrict__ gsrc, const float* __restrict__ besrc,
    const float* __restrict__ msrc, const float* __restrict__ vsrc,
    float* wdst, float* offdst, int Din, int Dout, int t)
{
    for (int e = t; e < Din * Dout; e += 256) {
        int o = e & (Dout - 1);            // Dout is 64 or 128 (pow2)
        int c = e / Dout;
        float sc = gsrc[o] * rsqrtf(vsrc[o] + EPSV);
        wdst[c * Dout + o] = wsrc[o * Din + c] * sc;
    }
    for (int o = t; o < Dout; o += 256) {
        float sc = gsrc[o] * rsqrtf(vsrc[o] + EPSV);
        offdst[o] = (bsrc[o] - msrc[o]) * sc + besrc[o];
    }
}

__global__ void transpose_prep_kernel(const float* __restrict__ f,
    const float* __restrict__ w0, const float* __restrict__ b0,
    const float* __restrict__ g0, const float* __restrict__ be0,
    const float* __restrict__ m0, const float* __restrict__ v0,
    const float* __restrict__ w1, const float* __restrict__ b1,
    const float* __restrict__ g1, const float* __restrict__ be1,
    const float* __restrict__ m1, const float* __restrict__ v1,
    const float* __restrict__ w2, const float* __restrict__ b2,
    const float* __restrict__ g2, const float* __restrict__ be2,
    const float* __restrict__ m2, const float* __restrict__ v2)
{
    __shared__ float tile[32][33];
    int b  = blockIdx.z;
    int c0 = blockIdx.y * 32;
    int n0 = blockIdx.x * 32;
    int tx = threadIdx.x, ty = threadIdx.y;
    int t  = ty * 32 + tx;                 // 0..255

    if (blockIdx.y == 0 && blockIdx.z == 0) {
        if (blockIdx.x == 0)
            fold_layer(w0, b0, g0, be0, m0, v0, g_wT0, g_off0, D0, D1, t);
        else if (blockIdx.x == 1)
            fold_layer(w1, b1, g1, be1, m1, v1, g_wT1, g_off1, D1, D2, t);
        else if (blockIdx.x == 2)
            fold_layer(w2, b2, g2, be2, m2, v2, g_wT2, g_off2, D2, D3, t);
        else if (blockIdx.x == 3 && t < B_)
            g_progress[t] = 0;
    }

    #pragma unroll
    for (int i = ty; i < 32; i += 8)
        tile[i][tx] = f[((size_t)b * C_ + (c0 + i)) * N_ + n0 + tx];
    __syncthreads();
    #pragma unroll
    for (int i = ty; i < 32; i += 8)
        g_featT[((size_t)b * N_ + (n0 + i)) * C_ + c0 + tx] = tile[tx][i];
}

// ---------------------------------------------------------------------------
// Merged kernel: blocks 0..7 = FPS producers; blocks 8.. = ball+MLP consumers.
// ---------------------------------------------------------------------------
#define FPS_T 512
#define FPS_J 16
#define FPS_Q 8
#define FPS_W (FPS_T / 32)

#define SK 36
#define A_ELEMS   (68 * SK)
#define BB_ELEMS  (64 * SK)
#define GSTRIDE   (A_ELEMS + BB_ELEMS)
#define W_ELEMS   (D2 * D3)
#define GRP_BASE  W_ELEMS
#define INT_BASE  (W_ELEMS + 4 * GSTRIDE)
#define MERGED_SMEM (115 * 1024)         // force 1 block/SM

#define NCONS_BLK 4096                   // consumer blocks (4 centers each)

__global__ void __launch_bounds__(FPS_T, 1)
merged_kernel(const float* __restrict__ xyz,
              float* __restrict__ newxyz,
              float* __restrict__ outp)
{
    extern __shared__ float dyn[];
    const int t = threadIdx.x;
    const unsigned FULL = 0xffffffffu;

    if (blockIdx.x < B_) {
        // ======= FPS producer: R7 two-barrier lazy-argmax scheme =======
        float* sxn = dyn;                  // NEGATED coord mirrors
        float* syn = dyn + N_;
        float* szn = dyn + 2 * N_;
        uint* swv      = (uint*)(dyn + 3 * N_);    // [2][16] warp max bits
        int*  sIdxSlot = (int*)(swv + 2 * FPS_W);  // [2] argmax index slots

        const int b    = blockIdx.x;
        const int lane = t & 31;
        const int w    = t >> 5;
        const float* X = xyz + (size_t)b * N_ * 3;

        ull pX[FPS_Q], pY[FPS_Q], pZ[FPS_Q];
        uint ddu[FPS_J];
        const uint INF_BITS = __float_as_uint(1e10f);
        #pragma unroll
        for (int q = 0; q < FPS_Q; q++) {
            int p0 = t + (2 * q) * FPS_T;
            int p1 = t + (2 * q + 1) * FPS_T;
            float x0 = X[p0 * 3 + 0], y0 = X[p0 * 3 + 1], z0 = X[p0 * 3 + 2];
            float x1 = X[p1 * 3 + 0], y1 = X[p1 * 3 + 1], z1 = X[p1 * 3 + 2];
            pX[q] = pack2(x0, x1); pY[q] = pack2(y0, y1); pZ[q] = pack2(z0, z1);
            sxn[p0] = -x0; syn[p0] = -y0; szn[p0] = -z0;
            sxn[p1] = -x1; syn[p1] = -y1; szn[p1] = -z1;
            ddu[2 * q] = INF_BITS; ddu[2 * q + 1] = INF_BITS;
        }
        if (t == 0) { sIdxSlot[0] = 0x7fffffff; sIdxSlot[1] = 0x7fffffff; }
        __syncthreads();

        int cidx = 0;
        if (t == 0) {
            float* o = newxyz + (size_t)b * S_ * 3;
            o[0] = -sxn[0]; o[1] = -syn[0]; o[2] = -szn[0];
        }

        for (int i = 0; i < S_; i++) {
            const int buf = i & 1;
            const float nx = sxn[cidx], ny = syn[cidx], nz = szn[cidx]; // -c
            const ull ncx = pack2(nx, nx);
            const ull ncy = pack2(ny, ny);
            const ull ncz = pack2(nz, nz);

            #pragma unroll
            for (int q = 0; q < FPS_Q; q++) {
                ull dX = add2_(pX[q], ncx);
                ull dY = add2_(pY[q], ncy);
                ull dZ = add2_(pZ[q], ncz);
                ull d2 = add2_(add2_(mul2_(dX, dX), mul2_(dY, dY)), mul2_(dZ, dZ));
                float dlo, dhi; unpack2(d2, dlo, dhi);
                ddu[2 * q]     = min(ddu[2 * q],     __float_as_uint(dlo));
                ddu[2 * q + 1] = min(ddu[2 * q + 1], __float_as_uint(dhi));
            }
            // per-thread max tree (ALU pipe)
            uint m0 = max(max(ddu[0], ddu[1]),   max(ddu[2], ddu[3]));
            uint m1 = max(max(ddu[4], ddu[5]),   max(ddu[6], ddu[7]));
            uint m2 = max(max(ddu[8], ddu[9]),   max(ddu[10], ddu[11]));
            uint m3 = max(max(ddu[12], ddu[13]), max(ddu[14], ddu[15]));
            uint bvu = max(max(m0, m1), max(m2, m3));

            // value-only warp reduction
            uint wmax = __reduce_max_sync(FULL, bvu);
            if (lane == 0) swv[buf * FPS_W + w] = wmax;
            __syncthreads();                          // bar1

            // block max, computed redundantly in every warp
            uint v = (lane < FPS_W) ? swv[buf * FPS_W + lane] : 0u;
            uint gbits = __reduce_max_sync(FULL, v);

            // reset the other slot for the NEXT iteration (ordered by bar1/bar2)
            if (t == 0) sIdxSlot[buf ^ 1] = 0x7fffffff;

            // lazy index recovery: only block-max holders scan their 16 dd
            if (bvu == gbits) {
                int myi = 0x7fffffff;
                #pragma unroll
                for (int j = FPS_J - 1; j >= 0; j--)
                    if (ddu[j] == gbits) myi = t + j * FPS_T;  // descending: min j
                atomicMin(&sIdxSlot[buf], myi);
            }
            __syncthreads();                          // bar2
            cidx = sIdxSlot[buf];

            if (t == 0) {
                if (i < S_ - 1) {
                    float* o = newxyz + ((size_t)b * S_ + i + 1) * 3;
                    o[0] = -sxn[cidx]; o[1] = -syn[cidx]; o[2] = -szn[cidx];
                }
                if ((i & 7) == 7) {
                    int vis = (i < S_ - 1) ? (i + 2) : S_;
                    st_release(&g_progress[b], vis);
                }
            }
        }
        return;
    }

    // =================== consumer: ball query + MLP for 4 centers ===================
    const int cb = blockIdx.x - B_;           // 0..4095
    const int b  = cb & 7;                    // batch (interleaved)
    const int s0 = (cb >> 3) * 4;             // first center of this block

    float* W  = dyn;                          // [8192]
    const int gg  = t >> 7;                   // group 0..3
    const int gt  = t & 127;                  // thread within group
    const int gw  = gt >> 5;                  // warp within group
    const int lane = t & 31;

    float* A  = dyn + GRP_BASE + gg * GSTRIDE;
    float* Bb = A + A_ELEMS;
    int* iBase = (int*)(dyn + INT_BASE);
    int* sBall = iBase + gg * 128;
    int* sCnt  = iBase + 512 + gg * 4;
    int* sIdxG = iBase + 528 + gg * K_;

    if (t == 0) {
        while (ld_acquire(&g_progress[b]) < s0 + 4) __nanosleep(64);
    }
    __syncthreads();

    const int s   = s0 + gg;
    const int cid = b * S_ + s;
    const float* cc = newxyz + (size_t)cid * 3;
    const float cx = cc[0], cy = cc[1], cz = cc[2];
    const float* X = xyz + (size_t)b * N_ * 3;

    // --- ball query: warp gw scans [gw*2048, (gw+1)*2048) ---
    {
        int myCnt = 0;
        const unsigned lt = (1u << lane) - 1u;
        const int nEnd = (gw + 1) * (N_ / 4);
        for (int n0 = gw * (N_ / 4); n0 < nEnd && myCnt < K_; n0 += 32) {
            int p = n0 + lane;
            float dx = X[p * 3 + 0] - cx;
            float dy = X[p * 3 + 1] - cy;
            float dz = X[p * 3 + 2] - cz;
            float d  = fmaf(dz, dz, fmaf(dy, dy, dx * dx));
            bool inside = (d <= R2);
            unsigned m = __ballot_sync(FULL, inside);
            if (m) {
                int pos = myCnt + __popc(m & lt);
                if (inside && pos < K_) sBall[gw * K_ + pos] = p;
                myCnt += __popc(m);
            }
        }
        if (lane == 0) sCnt[gw] = min(myCnt, K_);
    }
    __syncthreads();

    // --- merge first-32 in ascending order; pad with overall first hit ---
    if (gt < K_) {
        int c0 = sCnt[0], c1 = sCnt[1], c2 = sCnt[2], c3 = sCnt[3];
        int o1 = c0, o2 = c0 + c1, o3 = o2 + c2, tot = o3 + c3;
        int k = gt, idx;
        if (k < tot) {
            if (k < o1)      idx = sBall[k];
            else if (k < o2) idx = sBall[32 + (k - o1)];
            else if (k < o3) idx = sBall[64 + (k - o2)];
            else             idx = sBall[96 + (k - o3)];
        } else {
            int fw = c0 ? 0 : (c1 ? 1 : (c2 ? 2 : 3));
            idx = sBall[fw * 32];
        }
        sIdxG[gt] = idx;
        const float* P = X + (size_t)idx * 3;
        A[0 * SK + gt] = P[0] - cx;
        A[1 * SK + gt] = P[1] - cy;
        A[2 * SK + gt] = P[2] - cz;
    }
    __syncthreads();

    for (int idx = gt; idx < K_ * C_; idx += 128) {
        int k = idx >> 6, c = idx & 63;
        A[(3 + c) * SK + k] = g_featT[((size_t)b * N_ + sIdxG[k]) * C_ + c];
    }
    for (int idx = t * 4; idx < D0 * D1; idx += FPS_T * 4)
        *(float4*)&W[idx] = *(const float4*)&g_wT0[idx];
    __syncthreads();

    const int kg = gt >> 4;
    const int k0 = kg * 4;
    const int og = gt & 15;

    // ================= layer 1: 67 -> 64 =================
    {
        const int o0 = og * 4;
        ull a01[4], a23[4];
        const ull z = pack2(0.0f, 0.0f);
        #pragma unroll
        for (int o = 0; o < 4; o++) { a01[o] = z; a23[o] = z; }
        #pragma unroll 4
        for (int c = 0; c < D0; c++) {
            double2 iv = *(double2*)&A[c * SK + k0];
            ull i01 = __double_as_longlong(iv.x);
            ull i23 = __double_as_longlong(iv.y);
            float4 wv = *(float4*)&W[c * D1 + o0];
            ull w2[4] = {pack2(wv.x, wv.x), pack2(wv.y, wv.y),
                         pack2(wv.z, wv.z), pack2(wv.w, wv.w)};
            #pragma unroll
            for (int o = 0; o < 4; o++) {
                a01[o] = fma2_(i01, w2[o], a01[o]);
                a23[o] = fma2_(i23, w2[o], a23[o]);
            }
        }
        float4 off = *(const float4*)&g_off0[o0];
        const float off4[4] = {off.x, off.y, off.z, off.w};
        __syncthreads();
        #pragma unroll
        for (int o = 0; o < 4; o++) {
            float4 v; float lo, hi;
            unpack2(a01[o], lo, hi);
            v.x = fmaxf(lo + off4[o], 0.0f);
            v.y = fmaxf(hi + off4[o], 0.0f);
            unpack2(a23[o], lo, hi);
            v.z = fmaxf(lo + off4[o], 0.0f);
            v.w = fmaxf(hi + off4[o], 0.0f);
            *(float4*)&Bb[(o0 + o) * SK + k0] = v;
        }
    }
    __syncthreads();
    for (int idx = t * 4; idx < D1 * D2; idx += FPS_T * 4)
        *(float4*)&W[idx] = *(const float4*)&g_wT1[idx];
    __syncthreads();

    // ================= layer 2: 64 -> 64 (Bb -> A) =================
    {
        const int o0 = og * 4;
        ull a01[4], a23[4];
        const ull z = pack2(0.0f, 0.0f);
        #pragma unroll
        for (int o = 0; o < 4; o++) { a01[o] = z; a23[o] = z; }
        #pragma unroll 4
        for (int c = 0; c < D1; c++) {
            double2 iv = *(double2*)&Bb[c * SK + k0];
            ull i01 = __double_as_longlong(iv.x);
            ull i23 = __double_as_longlong(iv.y);
            float4 wv = *(float4*)&W[c * D2 + o0];
            ull w2[4] = {pack2(wv.x, wv.x), pack2(wv.y, wv.y),
                         pack2(wv.z, wv.z), pack2(wv.w, wv.w)};
            #pragma unroll
            for (int o = 0; o < 4; o++) {
                a01[o] = fma2_(i01, w2[o], a01[o]);
                a23[o] = fma2_(i23, w2[o], a23[o]);
            }
        }
        float4 off = *(const float4*)&g_off1[o0];
        const float off4[4] = {off.x, off.y, off.z, off.w};
        __syncthreads();
        #pragma unroll
        for (int o = 0; o < 4; o++) {
            float4 v; float lo, hi;
            unpack2(a01[o], lo, hi);
            v.x = fmaxf(lo + off4[o], 0.0f);
            v.y = fmaxf(hi + off4[o], 0.0f);
            unpack2(a23[o], lo, hi);
            v.z = fmaxf(lo + off4[o], 0.0f);
            v.w = fmaxf(hi + off4[o], 0.0f);
            *(float4*)&A[(o0 + o) * SK + k0] = v;
        }
    }
    __syncthreads();
    for (int idx = t * 4; idx < D2 * D3; idx += FPS_T * 4)
        *(float4*)&W[idx] = *(const float4*)&g_wT2[idx];
    __syncthreads();

    // ================= layer 3: 64 -> 128, max over k =================
    {
        const int o0 = og * 8;
        ull a01[8], a23[8];
        const ull z = pack2(0.0f, 0.0f);
        #pragma unroll
        for (int o = 0; o < 8; o++) { a01[o] = z; a23[o] = z; }
        #pragma unroll 2
        for (int c = 0; c < D2; c++) {
            double2 iv = *(double2*)&A[c * SK + k0];
            ull i01 = __double_as_longlong(iv.x);
            ull i23 = __double_as_longlong(iv.y);
            float4 wv0 = *(float4*)&W[c * D3 + o0];
            float4 wv1 = *(float4*)&W[c * D3 + o0 + 4];
            ull w2[8] = {pack2(wv0.x, wv0.x), pack2(wv0.y, wv0.y),
                         pack2(wv0.z, wv0.z), pack2(wv0.w, wv0.w),
                         pack2(wv1.x, wv1.x), pack2(wv1.y, wv1.y),
                         pack2(wv1.z, wv1.z), pack2(wv1.w, wv1.w)};
            #pragma unroll
            for (int o = 0; o < 8; o++) {
                a01[o] = fma2_(i01, w2[o], a01[o]);
                a23[o] = fma2_(i23, w2[o], a23[o]);
            }
        }
        __syncthreads();
        #pragma unroll
        for (int o = 0; o < 8; o++) {
            float off = g_off2[o0 + o];
            float l0, h0, l1, h1;
            unpack2(a01[o], l0, h0);
            unpack2(a23[o], l1, h1);
            float m = fmaxf(fmaxf(l0, h0), fmaxf(l1, h1));
            Bb[kg * D3 + o0 + o] = fmaxf(m + off, 0.0f);
        }
    }
    __syncthreads();
    if (gt < D3) {
        float v = Bb[gt];
        #pragma unroll
        for (int g = 1; g < 8; g++) v = fmaxf(v, Bb[g * D3 + gt]);
        outp[((size_t)b * D3 + gt) * S_ + s] = v;
    }
}

// ---------------------------------------------------------------------------
// Launch
// ---------------------------------------------------------------------------
extern "C" void kernel_launch(void* const* d_in, const int* in_sizes, int n_in,
                              void* d_out, int out_size)
{
    const float* xyz  = (const float*)d_in[0];
    const float* feat = (const float*)d_in[1];

    float* out     = (float*)d_out;
    float* newxyz  = out;                       // (8, 2048, 3)
    float* mlpOut  = out + (size_t)B_ * S_ * 3; // (8, 128, 2048)

    cudaFuncSetAttribute(merged_kernel, cudaFuncAttributeMaxDynamicSharedMemorySize,
                         MERGED_SMEM);

    dim3 tg(N_ / 32, C_ / 32, B_);
    transpose_prep_kernel<<<tg, dim3(32, 8)>>>(feat,
        (const float*)d_in[2],  (const float*)d_in[3],  (const float*)d_in[4],
        (const float*)d_in[5],  (const float*)d_in[6],  (const float*)d_in[7],
        (const float*)d_in[8],  (const float*)d_in[9],  (const float*)d_in[10],
        (const float*)d_in[11], (const float*)d_in[12], (const float*)d_in[13],
        (const float*)d_in[14], (const float*)d_in[15], (const float*)d_in[16],
        (const float*)d_in[17], (const float*)d_in[18], (const float*)d_in[19]);

    merged_kernel<<<B_ + NCONS_BLK, FPS_T, MERGED_SMEM>>>(xyz, newxyz, mlpOut);
}